// round 3
// baseline (speedup 1.0000x reference)
#include <cuda_runtime.h>
#include <cstdint>
#include <math.h>

#define T_TOK 8192
#define DIM   1024
#define FF    4096
#define NE    8
#define TOPK  2

// ---------------- device scratch (no cudaMalloc allowed) ----------------
__device__ int   g_counts[NE];
__device__ int   g_offsets[NE + 1];
__device__ int   g_cursor[NE];
__device__ int   g_tok_e[T_TOK * TOPK];
__device__ float g_tok_w[T_TOK * TOPK];
__device__ int   g_tok[T_TOK * TOPK];    // token id per flat slot
__device__ float g_wt[T_TOK * TOPK];     // routing weight per flat slot
__device__ float g_H[(size_t)T_TOK * TOPK * FF];   // 268 MB intermediate

// ---------------- helpers ----------------
__device__ __forceinline__ uint32_t f2tf32(float f) {
    uint32_t r;
    asm("cvt.rna.tf32.f32 %0, %1;" : "=r"(r) : "f"(f));
    return r;
}

__device__ __forceinline__ void mma_tf32(float* c, const uint32_t* a, uint32_t b0, uint32_t b1) {
    asm volatile(
        "mma.sync.aligned.m16n8k8.row.col.f32.tf32.tf32.f32 "
        "{%0,%1,%2,%3}, {%4,%5,%6,%7}, {%8,%9}, {%0,%1,%2,%3};\n"
        : "+f"(c[0]), "+f"(c[1]), "+f"(c[2]), "+f"(c[3])
        : "r"(a[0]), "r"(a[1]), "r"(a[2]), "r"(a[3]), "r"(b0), "r"(b1));
}

__device__ __forceinline__ float silu_f(float g) {
    return g / (1.0f + __expf(-g));
}

// ---------------- kernel 0: zero output + counters ----------------
__global__ void moe_zero_kernel(float4* __restrict__ out4) {
    const int n = (T_TOK * DIM) / 4;
    int i = blockIdx.x * blockDim.x + threadIdx.x;
    for (; i < n; i += gridDim.x * blockDim.x)
        out4[i] = make_float4(0.f, 0.f, 0.f, 0.f);
    if (blockIdx.x == 0 && threadIdx.x < NE)
        g_counts[threadIdx.x] = 0;
}

// ---------------- kernel 1: gating (1 warp per token, full fp32) ----------------
__global__ void moe_gate_kernel(const float* __restrict__ x, const float* __restrict__ gw) {
    int warp = (blockIdx.x * blockDim.x + threadIdx.x) >> 5;
    int lane = threadIdx.x & 31;
    if (warp >= T_TOK) return;
    const float* xr = x + (size_t)warp * DIM;

    float acc[NE];
#pragma unroll
    for (int e = 0; e < NE; e++) acc[e] = 0.f;

    for (int d = lane; d < DIM; d += 32) {
        float xv = xr[d];
        const float* g = gw + d * NE;
#pragma unroll
        for (int e = 0; e < NE; e++) acc[e] += xv * g[e];
    }
#pragma unroll
    for (int e = 0; e < NE; e++) {
#pragma unroll
        for (int o = 16; o > 0; o >>= 1)
            acc[e] += __shfl_xor_sync(0xffffffffu, acc[e], o);
    }
    if (lane == 0) {
        int i1 = 0; float v1 = acc[0];
#pragma unroll
        for (int e = 1; e < NE; e++) if (acc[e] > v1) { v1 = acc[e]; i1 = e; }
        int i2 = -1; float v2 = -INFINITY;
#pragma unroll
        for (int e = 0; e < NE; e++) if (e != i1 && acc[e] > v2) { v2 = acc[e]; i2 = e; }
        float e2 = expf(v2 - v1);   // v1 >= v2
        float inv = 1.0f / (1.0f + e2);
        g_tok_e[warp * 2 + 0] = i1;
        g_tok_e[warp * 2 + 1] = i2;
        g_tok_w[warp * 2 + 0] = inv;
        g_tok_w[warp * 2 + 1] = e2 * inv;
        atomicAdd(&g_counts[i1], 1);
        atomicAdd(&g_counts[i2], 1);
    }
}

// ---------------- kernel 2: offsets (tiny) ----------------
__global__ void moe_offset_kernel() {
    int o = 0;
    g_offsets[0] = 0;
#pragma unroll
    for (int e = 0; e < NE; e++) {
        o += g_counts[e];
        g_offsets[e + 1] = o;
        g_cursor[e] = g_offsets[e];
    }
}

// ---------------- kernel 3: scatter tokens into per-expert slots ----------------
__global__ void moe_scatter_kernel() {
    int t = blockIdx.x * blockDim.x + threadIdx.x;
    if (t >= T_TOK) return;
#pragma unroll
    for (int k = 0; k < TOPK; k++) {
        int e = g_tok_e[t * 2 + k];
        int slot = atomicAdd(&g_cursor[e], 1);
        g_tok[slot] = t;
        g_wt[slot] = g_tok_w[t * 2 + k];
    }
}

// ---------------- GEMM config ----------------
// Block tile: 128(M) x 64(N), BK=16, 256 threads, warp grid 4(M) x 2(N), warp tile 32x32.
// smem stride 20 (16 + 4 pad) -> conflict-free fragment reads.
#define STR 20

// ---------------- kernel 4: GEMM1 fused (x@w1, x@w3) + SwiGLU -> g_H ----------------
__global__ __launch_bounds__(256, 1)
void moe_gemm1_kernel(const float* __restrict__ x,
                      const float* __restrict__ w1,
                      const float* __restrict__ w3) {
    int bid = blockIdx.x;
    int mt = bid & 63;              // m fastest: concurrent blocks share B slab in L2
    int nt = (bid >> 6) & 63;       // 64 n-tiles of 64 -> F=4096
    int e  = bid >> 12;

    int row0    = g_offsets[e] + mt * 128;
    int row_end = g_offsets[e + 1];
    if (row0 >= row_end) return;
    int rows = min(128, row_end - row0);

    __shared__ uint32_t sA[2][128 * STR];
    __shared__ uint32_t sB1[2][64 * STR];
    __shared__ uint32_t sB3[2][64 * STR];
    __shared__ int sTok[128];

    int tid = threadIdx.x;
    if (tid < 128) sTok[tid] = (tid < rows) ? g_tok[row0 + tid] : -1;
    __syncthreads();

    const float* w1e = w1 + (size_t)e * DIM * FF;
    const float* w3e = w3 + (size_t)e * DIM * FF;
    const int ncol0 = nt * 64;

    int warp = tid >> 5, lane = tid & 31;
    int wm = warp & 3, wn = warp >> 2;
    int mrow = wm * 32, ncol = wn * 32;
    int grp = lane >> 2, tig = lane & 3;

    float accG[2][4][4], accV[2][4][4];
#pragma unroll
    for (int mi = 0; mi < 2; mi++)
#pragma unroll
        for (int ni = 0; ni < 4; ni++)
#pragma unroll
            for (int q = 0; q < 4; q++) { accG[mi][ni][q] = 0.f; accV[mi][ni][q] = 0.f; }

    // --- stage 0 fill ---
    {
#pragma unroll
        for (int i = 0; i < 2; i++) {
            int idx = tid + i * 256;
            int r = idx >> 2, c4 = idx & 3;
            int tok = sTok[r];
            float4 v = make_float4(0.f, 0.f, 0.f, 0.f);
            if (tok >= 0) v = *(const float4*)(x + (size_t)tok * DIM + c4 * 4);
            uint32_t* d = &sA[0][r * STR + c4 * 4];
            d[0] = f2tf32(v.x); d[1] = f2tf32(v.y); d[2] = f2tf32(v.z); d[3] = f2tf32(v.w);
        }
        int kb = tid >> 4, n4 = tid & 15;
        float4 b1v = *(const float4*)(w1e + (size_t)kb * FF + ncol0 + n4 * 4);
        float4 b3v = *(const float4*)(w3e + (size_t)kb * FF + ncol0 + n4 * 4);
#pragma unroll
        for (int j = 0; j < 4; j++) {
            sB1[0][(n4 * 4 + j) * STR + kb] = f2tf32((&b1v.x)[j]);
            sB3[0][(n4 * 4 + j) * STR + kb] = f2tf32((&b3v.x)[j]);
        }
    }
    __syncthreads();

    const int KT = DIM / 16;   // 64
    for (int kt = 0; kt < KT; kt++) {
        int cur = kt & 1;
        bool nx = (kt + 1 < KT);
        int k0n = (kt + 1) * 16;
        float4 pa0, pa1, pb1, pb3;
        if (nx) {
            {
                int idx = tid;
                int r = idx >> 2, c4 = idx & 3;
                int tok = sTok[r];
                pa0 = (tok >= 0) ? *(const float4*)(x + (size_t)tok * DIM + k0n + c4 * 4)
                                 : make_float4(0.f, 0.f, 0.f, 0.f);
            }
            {
                int idx = tid + 256;
                int r = idx >> 2, c4 = idx & 3;
                int tok = sTok[r];
                pa1 = (tok >= 0) ? *(const float4*)(x + (size_t)tok * DIM + k0n + c4 * 4)
                                 : make_float4(0.f, 0.f, 0.f, 0.f);
            }
            int kb = tid >> 4, n4 = tid & 15;
            pb1 = *(const float4*)(w1e + (size_t)(k0n + kb) * FF + ncol0 + n4 * 4);
            pb3 = *(const float4*)(w3e + (size_t)(k0n + kb) * FF + ncol0 + n4 * 4);
        }
        // --- compute on cur ---
#pragma unroll
        for (int kk = 0; kk < 16; kk += 8) {
            uint32_t a[2][4];
#pragma unroll
            for (int mi = 0; mi < 2; mi++) {
                const uint32_t* Ab = &sA[cur][(mrow + mi * 16 + grp) * STR + kk + tig];
                a[mi][0] = Ab[0];
                a[mi][1] = Ab[8 * STR];
                a[mi][2] = Ab[4];
                a[mi][3] = Ab[8 * STR + 4];
            }
#pragma unroll
            for (int ni = 0; ni < 4; ni++) {
                int cb = (ncol + ni * 8 + grp) * STR + kk + tig;
                uint32_t b10 = sB1[cur][cb], b11 = sB1[cur][cb + 4];
                uint32_t b30 = sB3[cur][cb], b31 = sB3[cur][cb + 4];
#pragma unroll
                for (int mi = 0; mi < 2; mi++) {
                    mma_tf32(accG[mi][ni], a[mi], b10, b11);
                    mma_tf32(accV[mi][ni], a[mi], b30, b31);
                }
            }
        }
        if (nx) {
            int ns = cur ^ 1;
            {
                int idx = tid; int r = idx >> 2, c4 = idx & 3;
                uint32_t* d = &sA[ns][r * STR + c4 * 4];
                d[0] = f2tf32(pa0.x); d[1] = f2tf32(pa0.y); d[2] = f2tf32(pa0.z); d[3] = f2tf32(pa0.w);
            }
            {
                int idx = tid + 256; int r = idx >> 2, c4 = idx & 3;
                uint32_t* d = &sA[ns][r * STR + c4 * 4];
                d[0] = f2tf32(pa1.x); d[1] = f2tf32(pa1.y); d[2] = f2tf32(pa1.z); d[3] = f2tf32(pa1.w);
            }
            int kb = tid >> 4, n4 = tid & 15;
#pragma unroll
            for (int j = 0; j < 4; j++) {
                sB1[ns][(n4 * 4 + j) * STR + kb] = f2tf32((&pb1.x)[j]);
                sB3[ns][(n4 * 4 + j) * STR + kb] = f2tf32((&pb3.x)[j]);
            }
            __syncthreads();
        }
    }

    // --- epilogue: SwiGLU -> g_H ---
#pragma unroll
    for (int mi = 0; mi < 2; mi++) {
#pragma unroll
        for (int ni = 0; ni < 4; ni++) {
            int r = mrow + mi * 16 + grp;
            int c = ncol + ni * 8 + tig * 2;
            size_t gc = (size_t)ncol0 + c;
            const float* g = accG[mi][ni];
            const float* v = accV[mi][ni];
            if (r < rows) {
                float h0 = silu_f(g[0]) * v[0];
                float h1 = silu_f(g[1]) * v[1];
                *(float2*)&g_H[(size_t)(row0 + r) * FF + gc] = make_float2(h0, h1);
            }
            int r2 = r + 8;
            if (r2 < rows) {
                float h2 = silu_f(g[2]) * v[2];
                float h3 = silu_f(g[3]) * v[3];
                *(float2*)&g_H[(size_t)(row0 + r2) * FF + gc] = make_float2(h2, h3);
            }
        }
    }
}

// ---------------- kernel 5: GEMM2 (H @ w2) scaled scatter-add ----------------
__global__ __launch_bounds__(256, 1)
void moe_gemm2_kernel(const float* __restrict__ w2, float* __restrict__ out) {
    int bid = blockIdx.x;
    int nt = bid & 15;              // n fastest: concurrent blocks share A/H slab in L2
    int mt = (bid >> 4) & 63;
    int e  = bid >> 10;

    int row0    = g_offsets[e] + mt * 128;
    int row_end = g_offsets[e + 1];
    if (row0 >= row_end) return;
    int rows = min(128, row_end - row0);

    __shared__ uint32_t sA[2][128 * STR];
    __shared__ uint32_t sB[2][64 * STR];
    __shared__ int   sTok[128];
    __shared__ float sWt[128];

    int tid = threadIdx.x;
    if (tid < 128) {
        bool ok = tid < rows;
        sTok[tid] = ok ? g_tok[row0 + tid] : -1;
        sWt[tid]  = ok ? g_wt[row0 + tid] : 0.f;
    }
    __syncthreads();

    const float* w2e = w2 + (size_t)e * FF * DIM;
    const int ncol0 = nt * 64;

    int warp = tid >> 5, lane = tid & 31;
    int wm = warp & 3, wn = warp >> 2;
    int mrow = wm * 32, ncol = wn * 32;
    int grp = lane >> 2, tig = lane & 3;

    float accC[2][4][4];
#pragma unroll
    for (int mi = 0; mi < 2; mi++)
#pragma unroll
        for (int ni = 0; ni < 4; ni++)
#pragma unroll
            for (int q = 0; q < 4; q++) accC[mi][ni][q] = 0.f;

    // --- stage 0 fill ---
    {
#pragma unroll
        for (int i = 0; i < 2; i++) {
            int idx = tid + i * 256;
            int r = idx >> 2, c4 = idx & 3;
            float4 v = make_float4(0.f, 0.f, 0.f, 0.f);
            if (r < rows) v = *(const float4*)(&g_H[(size_t)(row0 + r) * FF + c4 * 4]);
            uint32_t* d = &sA[0][r * STR + c4 * 4];
            d[0] = f2tf32(v.x); d[1] = f2tf32(v.y); d[2] = f2tf32(v.z); d[3] = f2tf32(v.w);
        }
        int kb = tid >> 4, n4 = tid & 15;
        float4 bv = *(const float4*)(w2e + (size_t)kb * DIM + ncol0 + n4 * 4);
#pragma unroll
        for (int j = 0; j < 4; j++)
            sB[0][(n4 * 4 + j) * STR + kb] = f2tf32((&bv.x)[j]);
    }
    __syncthreads();

    const int KT = FF / 16;   // 256
    for (int kt = 0; kt < KT; kt++) {
        int cur = kt & 1;
        bool nx = (kt + 1 < KT);
        int k0n = (kt + 1) * 16;
        float4 pa0, pa1, pb;
        if (nx) {
            {
                int idx = tid; int r = idx >> 2, c4 = idx & 3;
                pa0 = (r < rows) ? *(const float4*)(&g_H[(size_t)(row0 + r) * FF + k0n + c4 * 4])
                                 : make_float4(0.f, 0.f, 0.f, 0.f);
            }
            {
                int idx = tid + 256; int r = idx >> 2, c4 = idx & 3;
                pa1 = (r < rows) ? *(const float4*)(&g_H[(size_t)(row0 + r) * FF + k0n + c4 * 4])
                                 : make_float4(0.f, 0.f, 0.f, 0.f);
            }
            int kb = tid >> 4, n4 = tid & 15;
            pb = *(const float4*)(w2e + (size_t)(k0n + kb) * DIM + ncol0 + n4 * 4);
        }
#pragma unroll
        for (int kk = 0; kk < 16; kk += 8) {
            uint32_t a[2][4];
#pragma unroll
            for (int mi = 0; mi < 2; mi++) {
                const uint32_t* Ab = &sA[cur][(mrow + mi * 16 + grp) * STR + kk + tig];
                a[mi][0] = Ab[0];
                a[mi][1] = Ab[8 * STR];
                a[mi][2] = Ab[4];
                a[mi][3] = Ab[8 * STR + 4];
            }
#pragma unroll
            for (int ni = 0; ni < 4; ni++) {
                int cb = (ncol + ni * 8 + grp) * STR + kk + tig;
                uint32_t b0 = sB[cur][cb], b1 = sB[cur][cb + 4];
#pragma unroll
                for (int mi = 0; mi < 2; mi++)
                    mma_tf32(accC[mi][ni], a[mi], b0, b1);
            }
        }
        if (nx) {
            int ns = cur ^ 1;
            {
                int idx = tid; int r = idx >> 2, c4 = idx & 3;
                uint32_t* d = &sA[ns][r * STR + c4 * 4];
                d[0] = f2tf32(pa0.x); d[1] = f2tf32(pa0.y); d[2] = f2tf32(pa0.z); d[3] = f2tf32(pa0.w);
            }
            {
                int idx = tid + 256; int r = idx >> 2, c4 = idx & 3;
                uint32_t* d = &sA[ns][r * STR + c4 * 4];
                d[0] = f2tf32(pa1.x); d[1] = f2tf32(pa1.y); d[2] = f2tf32(pa1.z); d[3] = f2tf32(pa1.w);
            }
            int kb = tid >> 4, n4 = tid & 15;
#pragma unroll
            for (int j = 0; j < 4; j++)
                sB[ns][(n4 * 4 + j) * STR + kb] = f2tf32((&pb.x)[j]);
            __syncthreads();
        }
    }

    // --- epilogue: weight * acc, atomic scatter-add into out ---
#pragma unroll
    for (int mi = 0; mi < 2; mi++) {
#pragma unroll
        for (int ni = 0; ni < 4; ni++) {
            int r = mrow + mi * 16 + grp;
            int c = ncol + ni * 8 + tig * 2;
            size_t gc = (size_t)ncol0 + c;
            const float* a = accC[mi][ni];
            if (r < rows) {
                int tok = sTok[r]; float wq = sWt[r];
                float* p = &out[(size_t)tok * DIM + gc];
                atomicAdd(p + 0, a[0] * wq);
                atomicAdd(p + 1, a[1] * wq);
            }
            int r2 = r + 8;
            if (r2 < rows) {
                int tok = sTok[r2]; float wq = sWt[r2];
                float* p = &out[(size_t)tok * DIM + gc];
                atomicAdd(p + 0, a[2] * wq);
                atomicAdd(p + 1, a[3] * wq);
            }
        }
    }
}

// ---------------- launch ----------------
extern "C" void kernel_launch(void* const* d_in, const int* in_sizes, int n_in,
                              void* d_out, int out_size) {
    (void)in_sizes; (void)n_in; (void)out_size;
    const float* x  = (const float*)d_in[0];
    const float* gw = (const float*)d_in[1];
    const float* w1 = (const float*)d_in[2];
    const float* w3 = (const float*)d_in[3];
    const float* w2 = (const float*)d_in[4];
    float* out = (float*)d_out;

    moe_zero_kernel<<<2048, 256>>>((float4*)out);
    moe_gate_kernel<<<T_TOK / 8, 256>>>(x, gw);
    moe_offset_kernel<<<1, 1>>>();
    moe_scatter_kernel<<<T_TOK / 256, 256>>>();
    // GEMM1: grid = E(8) * n_tiles(64) * m_tiles_max(64), m fastest
    moe_gemm1_kernel<<<8 * 64 * 64, 256>>>(x, w1, w3);
    // GEMM2: grid = E(8) * m_tiles_max(64) * n_tiles(16), n fastest
    moe_gemm2_kernel<<<8 * 64 * 16, 256>>>(w2, out);
}

// round 4
// speedup vs baseline: 1.4057x; 1.4057x over previous
#include <cuda_runtime.h>
#include <cstdint>
#include <math.h>

#define T_TOK 8192
#define DIM   1024
#define FF    4096
#define NE    8
#define TOPK  2

// ---------------- device scratch (no cudaMalloc allowed) ----------------
__device__ int   g_counts[NE];
__device__ int   g_offsets[NE + 1];
__device__ int   g_cursor[NE];
__device__ int   g_tok_e[T_TOK * TOPK];
__device__ float g_tok_w[T_TOK * TOPK];
__device__ int   g_tok[T_TOK * TOPK];    // token id per flat slot
__device__ float g_wt[T_TOK * TOPK];     // routing weight per flat slot
__device__ float g_H[(size_t)T_TOK * TOPK * FF];   // 268 MB intermediate

// ---------------- helpers ----------------
__device__ __forceinline__ uint32_t f2tf32(float f) {
    uint32_t r;
    asm("cvt.rna.tf32.f32 %0, %1;" : "=r"(r) : "f"(f));
    return r;
}

__device__ __forceinline__ void mma_tf32(float* c, const uint32_t* a, uint32_t b0, uint32_t b1) {
    asm volatile(
        "mma.sync.aligned.m16n8k8.row.col.f32.tf32.tf32.f32 "
        "{%0,%1,%2,%3}, {%4,%5,%6,%7}, {%8,%9}, {%0,%1,%2,%3};\n"
        : "+f"(c[0]), "+f"(c[1]), "+f"(c[2]), "+f"(c[3])
        : "r"(a[0]), "r"(a[1]), "r"(a[2]), "r"(a[3]), "r"(b0), "r"(b1));
}

__device__ __forceinline__ float silu_f(float g) {
    return g / (1.0f + __expf(-g));
}

// ---------------- kernel 0: zero output + counters ----------------
__global__ void moe_zero_kernel(float4* __restrict__ out4) {
    const int n = (T_TOK * DIM) / 4;
    int i = blockIdx.x * blockDim.x + threadIdx.x;
    for (; i < n; i += gridDim.x * blockDim.x)
        out4[i] = make_float4(0.f, 0.f, 0.f, 0.f);
    if (blockIdx.x == 0 && threadIdx.x < NE)
        g_counts[threadIdx.x] = 0;
}

// ---------------- kernel 1: gating (1 warp per token, full fp32) ----------------
__global__ void moe_gate_kernel(const float* __restrict__ x, const float* __restrict__ gw) {
    int warp = (blockIdx.x * blockDim.x + threadIdx.x) >> 5;
    int lane = threadIdx.x & 31;
    if (warp >= T_TOK) return;
    const float* xr = x + (size_t)warp * DIM;

    float acc[NE];
#pragma unroll
    for (int e = 0; e < NE; e++) acc[e] = 0.f;

    for (int d = lane; d < DIM; d += 32) {
        float xv = xr[d];
        const float* g = gw + d * NE;
#pragma unroll
        for (int e = 0; e < NE; e++) acc[e] += xv * g[e];
    }
#pragma unroll
    for (int e = 0; e < NE; e++) {
#pragma unroll
        for (int o = 16; o > 0; o >>= 1)
            acc[e] += __shfl_xor_sync(0xffffffffu, acc[e], o);
    }
    if (lane == 0) {
        int i1 = 0; float v1 = acc[0];
#pragma unroll
        for (int e = 1; e < NE; e++) if (acc[e] > v1) { v1 = acc[e]; i1 = e; }
        int i2 = -1; float v2 = -INFINITY;
#pragma unroll
        for (int e = 0; e < NE; e++) if (e != i1 && acc[e] > v2) { v2 = acc[e]; i2 = e; }
        float e2 = expf(v2 - v1);   // v1 >= v2
        float inv = 1.0f / (1.0f + e2);
        g_tok_e[warp * 2 + 0] = i1;
        g_tok_e[warp * 2 + 1] = i2;
        g_tok_w[warp * 2 + 0] = inv;
        g_tok_w[warp * 2 + 1] = e2 * inv;
        atomicAdd(&g_counts[i1], 1);
        atomicAdd(&g_counts[i2], 1);
    }
}

// ---------------- kernel 2: offsets (tiny) ----------------
__global__ void moe_offset_kernel() {
    int o = 0;
    g_offsets[0] = 0;
#pragma unroll
    for (int e = 0; e < NE; e++) {
        o += g_counts[e];
        g_offsets[e + 1] = o;
        g_cursor[e] = g_offsets[e];
    }
}

// ---------------- kernel 3: scatter tokens into per-expert slots ----------------
__global__ void moe_scatter_kernel() {
    int t = blockIdx.x * blockDim.x + threadIdx.x;
    if (t >= T_TOK) return;
#pragma unroll
    for (int k = 0; k < TOPK; k++) {
        int e = g_tok_e[t * 2 + k];
        int slot = atomicAdd(&g_cursor[e], 1);
        g_tok[slot] = t;
        g_wt[slot] = g_tok_w[t * 2 + k];
    }
}

// ---------------- GEMM config ----------------
// Block tile: 128(M) x 64(N), BK=16, 256 threads, warp grid 4(M) x 2(N), warp tile 32x32.
// smem stride 20 (16 + 4 pad) -> conflict-free fragment reads.
#define STR 20

// ---------------- kernel 4: GEMM1 fused (x@w1, x@w3) + SwiGLU -> g_H ----------------
__global__ __launch_bounds__(256, 1)
void moe_gemm1_kernel(const float* __restrict__ x,
                      const float* __restrict__ w1,
                      const float* __restrict__ w3) {
    int bid = blockIdx.x;
    int mt = bid & 63;              // m fastest: concurrent blocks share B slab in L2
    int nt = (bid >> 6) & 63;       // 64 n-tiles of 64 -> F=4096
    int e  = bid >> 12;

    int row0    = g_offsets[e] + mt * 128;
    int row_end = g_offsets[e + 1];
    if (row0 >= row_end) return;
    int rows = min(128, row_end - row0);

    __shared__ uint32_t sA[2][128 * STR];
    __shared__ uint32_t sB1[2][64 * STR];
    __shared__ uint32_t sB3[2][64 * STR];
    __shared__ int sTok[128];

    int tid = threadIdx.x;
    if (tid < 128) sTok[tid] = (tid < rows) ? g_tok[row0 + tid] : -1;
    __syncthreads();

    const float* w1e = w1 + (size_t)e * DIM * FF;
    const float* w3e = w3 + (size_t)e * DIM * FF;
    const int ncol0 = nt * 64;

    int warp = tid >> 5, lane = tid & 31;
    int wm = warp & 3, wn = warp >> 2;
    int mrow = wm * 32, ncol = wn * 32;
    int grp = lane >> 2, tig = lane & 3;

    float accG[2][4][4], accV[2][4][4];
#pragma unroll
    for (int mi = 0; mi < 2; mi++)
#pragma unroll
        for (int ni = 0; ni < 4; ni++)
#pragma unroll
            for (int q = 0; q < 4; q++) { accG[mi][ni][q] = 0.f; accV[mi][ni][q] = 0.f; }

    // --- stage 0 fill ---
    {
#pragma unroll
        for (int i = 0; i < 2; i++) {
            int idx = tid + i * 256;
            int r = idx >> 2, c4 = idx & 3;
            int tok = sTok[r];
            float4 v = make_float4(0.f, 0.f, 0.f, 0.f);
            if (tok >= 0) v = *(const float4*)(x + (size_t)tok * DIM + c4 * 4);
            uint32_t* d = &sA[0][r * STR + c4 * 4];
            d[0] = f2tf32(v.x); d[1] = f2tf32(v.y); d[2] = f2tf32(v.z); d[3] = f2tf32(v.w);
        }
        int kb = tid >> 4, n4 = tid & 15;
        float4 b1v = *(const float4*)(w1e + (size_t)kb * FF + ncol0 + n4 * 4);
        float4 b3v = *(const float4*)(w3e + (size_t)kb * FF + ncol0 + n4 * 4);
#pragma unroll
        for (int j = 0; j < 4; j++) {
            sB1[0][(n4 * 4 + j) * STR + kb] = f2tf32((&b1v.x)[j]);
            sB3[0][(n4 * 4 + j) * STR + kb] = f2tf32((&b3v.x)[j]);
        }
    }
    __syncthreads();

    const int KT = DIM / 16;   // 64
    for (int kt = 0; kt < KT; kt++) {
        int cur = kt & 1;
        bool nx = (kt + 1 < KT);
        int k0n = (kt + 1) * 16;
        float4 pa0, pa1, pb1, pb3;
        if (nx) {
            {
                int idx = tid;
                int r = idx >> 2, c4 = idx & 3;
                int tok = sTok[r];
                pa0 = (tok >= 0) ? *(const float4*)(x + (size_t)tok * DIM + k0n + c4 * 4)
                                 : make_float4(0.f, 0.f, 0.f, 0.f);
            }
            {
                int idx = tid + 256;
                int r = idx >> 2, c4 = idx & 3;
                int tok = sTok[r];
                pa1 = (tok >= 0) ? *(const float4*)(x + (size_t)tok * DIM + k0n + c4 * 4)
                                 : make_float4(0.f, 0.f, 0.f, 0.f);
            }
            int kb = tid >> 4, n4 = tid & 15;
            pb1 = *(const float4*)(w1e + (size_t)(k0n + kb) * FF + ncol0 + n4 * 4);
            pb3 = *(const float4*)(w3e + (size_t)(k0n + kb) * FF + ncol0 + n4 * 4);
        }
        // --- compute on cur ---
#pragma unroll
        for (int kk = 0; kk < 16; kk += 8) {
            uint32_t a[2][4];
#pragma unroll
            for (int mi = 0; mi < 2; mi++) {
                const uint32_t* Ab = &sA[cur][(mrow + mi * 16 + grp) * STR + kk + tig];
                a[mi][0] = Ab[0];
                a[mi][1] = Ab[8 * STR];
                a[mi][2] = Ab[4];
                a[mi][3] = Ab[8 * STR + 4];
            }
#pragma unroll
            for (int ni = 0; ni < 4; ni++) {
                int cb = (ncol + ni * 8 + grp) * STR + kk + tig;
                uint32_t b10 = sB1[cur][cb], b11 = sB1[cur][cb + 4];
                uint32_t b30 = sB3[cur][cb], b31 = sB3[cur][cb + 4];
#pragma unroll
                for (int mi = 0; mi < 2; mi++) {
                    mma_tf32(accG[mi][ni], a[mi], b10, b11);
                    mma_tf32(accV[mi][ni], a[mi], b30, b31);
                }
            }
        }
        if (nx) {
            int ns = cur ^ 1;
            {
                int idx = tid; int r = idx >> 2, c4 = idx & 3;
                uint32_t* d = &sA[ns][r * STR + c4 * 4];
                d[0] = f2tf32(pa0.x); d[1] = f2tf32(pa0.y); d[2] = f2tf32(pa0.z); d[3] = f2tf32(pa0.w);
            }
            {
                int idx = tid + 256; int r = idx >> 2, c4 = idx & 3;
                uint32_t* d = &sA[ns][r * STR + c4 * 4];
                d[0] = f2tf32(pa1.x); d[1] = f2tf32(pa1.y); d[2] = f2tf32(pa1.z); d[3] = f2tf32(pa1.w);
            }
            int kb = tid >> 4, n4 = tid & 15;
#pragma unroll
            for (int j = 0; j < 4; j++) {
                sB1[ns][(n4 * 4 + j) * STR + kb] = f2tf32((&pb1.x)[j]);
                sB3[ns][(n4 * 4 + j) * STR + kb] = f2tf32((&pb3.x)[j]);
            }
            __syncthreads();
        }
    }

    // --- epilogue: SwiGLU -> g_H ---
#pragma unroll
    for (int mi = 0; mi < 2; mi++) {
#pragma unroll
        for (int ni = 0; ni < 4; ni++) {
            int r = mrow + mi * 16 + grp;
            int c = ncol + ni * 8 + tig * 2;
            size_t gc = (size_t)ncol0 + c;
            const float* g = accG[mi][ni];
            const float* v = accV[mi][ni];
            if (r < rows) {
                float h0 = silu_f(g[0]) * v[0];
                float h1 = silu_f(g[1]) * v[1];
                *(float2*)&g_H[(size_t)(row0 + r) * FF + gc] = make_float2(h0, h1);
            }
            int r2 = r + 8;
            if (r2 < rows) {
                float h2 = silu_f(g[2]) * v[2];
                float h3 = silu_f(g[3]) * v[3];
                *(float2*)&g_H[(size_t)(row0 + r2) * FF + gc] = make_float2(h2, h3);
            }
        }
    }
}

// ---------------- kernel 5: GEMM2 (H @ w2) scaled scatter-add ----------------
__global__ __launch_bounds__(256, 1)
void moe_gemm2_kernel(const float* __restrict__ w2, float* __restrict__ out) {
    int bid = blockIdx.x;
    int nt = bid & 15;              // n fastest: concurrent blocks share A/H slab in L2
    int mt = (bid >> 4) & 63;
    int e  = bid >> 10;

    int row0    = g_offsets[e] + mt * 128;
    int row_end = g_offsets[e + 1];
    if (row0 >= row_end) return;
    int rows = min(128, row_end - row0);

    __shared__ uint32_t sA[2][128 * STR];
    __shared__ uint32_t sB[2][64 * STR];
    __shared__ int   sTok[128];
    __shared__ float sWt[128];

    int tid = threadIdx.x;
    if (tid < 128) {
        bool ok = tid < rows;
        sTok[tid] = ok ? g_tok[row0 + tid] : -1;
        sWt[tid]  = ok ? g_wt[row0 + tid] : 0.f;
    }
    __syncthreads();

    const float* w2e = w2 + (size_t)e * FF * DIM;
    const int ncol0 = nt * 64;

    int warp = tid >> 5, lane = tid & 31;
    int wm = warp & 3, wn = warp >> 2;
    int mrow = wm * 32, ncol = wn * 32;
    int grp = lane >> 2, tig = lane & 3;

    float accC[2][4][4];
#pragma unroll
    for (int mi = 0; mi < 2; mi++)
#pragma unroll
        for (int ni = 0; ni < 4; ni++)
#pragma unroll
            for (int q = 0; q < 4; q++) accC[mi][ni][q] = 0.f;

    // --- stage 0 fill ---
    {
#pragma unroll
        for (int i = 0; i < 2; i++) {
            int idx = tid + i * 256;
            int r = idx >> 2, c4 = idx & 3;
            float4 v = make_float4(0.f, 0.f, 0.f, 0.f);
            if (r < rows) v = *(const float4*)(&g_H[(size_t)(row0 + r) * FF + c4 * 4]);
            uint32_t* d = &sA[0][r * STR + c4 * 4];
            d[0] = f2tf32(v.x); d[1] = f2tf32(v.y); d[2] = f2tf32(v.z); d[3] = f2tf32(v.w);
        }
        int kb = tid >> 4, n4 = tid & 15;
        float4 bv = *(const float4*)(w2e + (size_t)kb * DIM + ncol0 + n4 * 4);
#pragma unroll
        for (int j = 0; j < 4; j++)
            sB[0][(n4 * 4 + j) * STR + kb] = f2tf32((&bv.x)[j]);
    }
    __syncthreads();

    const int KT = FF / 16;   // 256
    for (int kt = 0; kt < KT; kt++) {
        int cur = kt & 1;
        bool nx = (kt + 1 < KT);
        int k0n = (kt + 1) * 16;
        float4 pa0, pa1, pb;
        if (nx) {
            {
                int idx = tid; int r = idx >> 2, c4 = idx & 3;
                pa0 = (r < rows) ? *(const float4*)(&g_H[(size_t)(row0 + r) * FF + k0n + c4 * 4])
                                 : make_float4(0.f, 0.f, 0.f, 0.f);
            }
            {
                int idx = tid + 256; int r = idx >> 2, c4 = idx & 3;
                pa1 = (r < rows) ? *(const float4*)(&g_H[(size_t)(row0 + r) * FF + k0n + c4 * 4])
                                 : make_float4(0.f, 0.f, 0.f, 0.f);
            }
            int kb = tid >> 4, n4 = tid & 15;
            pb = *(const float4*)(w2e + (size_t)(k0n + kb) * DIM + ncol0 + n4 * 4);
        }
#pragma unroll
        for (int kk = 0; kk < 16; kk += 8) {
            uint32_t a[2][4];
#pragma unroll
            for (int mi = 0; mi < 2; mi++) {
                const uint32_t* Ab = &sA[cur][(mrow + mi * 16 + grp) * STR + kk + tig];
                a[mi][0] = Ab[0];
                a[mi][1] = Ab[8 * STR];
                a[mi][2] = Ab[4];
                a[mi][3] = Ab[8 * STR + 4];
            }
#pragma unroll
            for (int ni = 0; ni < 4; ni++) {
                int cb = (ncol + ni * 8 + grp) * STR + kk + tig;
                uint32_t b0 = sB[cur][cb], b1 = sB[cur][cb + 4];
#pragma unroll
                for (int mi = 0; mi < 2; mi++)
                    mma_tf32(accC[mi][ni], a[mi], b0, b1);
            }
        }
        if (nx) {
            int ns = cur ^ 1;
            {
                int idx = tid; int r = idx >> 2, c4 = idx & 3;
                uint32_t* d = &sA[ns][r * STR + c4 * 4];
                d[0] = f2tf32(pa0.x); d[1] = f2tf32(pa0.y); d[2] = f2tf32(pa0.z); d[3] = f2tf32(pa0.w);
            }
            {
                int idx = tid + 256; int r = idx >> 2, c4 = idx & 3;
                uint32_t* d = &sA[ns][r * STR + c4 * 4];
                d[0] = f2tf32(pa1.x); d[1] = f2tf32(pa1.y); d[2] = f2tf32(pa1.z); d[3] = f2tf32(pa1.w);
            }
            int kb = tid >> 4, n4 = tid & 15;
#pragma unroll
            for (int j = 0; j < 4; j++)
                sB[ns][(n4 * 4 + j) * STR + kb] = f2tf32((&pb.x)[j]);
            __syncthreads();
        }
    }

    // --- epilogue: weight * acc, atomic scatter-add into out ---
#pragma unroll
    for (int mi = 0; mi < 2; mi++) {
#pragma unroll
        for (int ni = 0; ni < 4; ni++) {
            int r = mrow + mi * 16 + grp;
            int c = ncol + ni * 8 + tig * 2;
            size_t gc = (size_t)ncol0 + c;
            const float* a = accC[mi][ni];
            if (r < rows) {
                int tok = sTok[r]; float wq = sWt[r];
                float* p = &out[(size_t)tok * DIM + gc];
                atomicAdd(p + 0, a[0] * wq);
                atomicAdd(p + 1, a[1] * wq);
            }
            int r2 = r + 8;
            if (r2 < rows) {
                int tok = sTok[r2]; float wq = sWt[r2];
                float* p = &out[(size_t)tok * DIM + gc];
                atomicAdd(p + 0, a[2] * wq);
                atomicAdd(p + 1, a[3] * wq);
            }
        }
    }
}

// ---------------- launch ----------------
extern "C" void kernel_launch(void* const* d_in, const int* in_sizes, int n_in,
                              void* d_out, int out_size) {
    (void)in_sizes; (void)n_in; (void)out_size;
    const float* x  = (const float*)d_in[0];
    const float* gw = (const float*)d_in[1];
    const float* w1 = (const float*)d_in[2];
    const float* w3 = (const float*)d_in[3];
    const float* w2 = (const float*)d_in[4];
    float* out = (float*)d_out;

    moe_zero_kernel<<<2048, 256>>>((float4*)out);
    moe_gate_kernel<<<T_TOK / 8, 256>>>(x, gw);
    moe_offset_kernel<<<1, 1>>>();
    moe_scatter_kernel<<<T_TOK / 256, 256>>>();
    // GEMM1: grid = E(8) * n_tiles(64) * m_tiles_max(64), m fastest
    moe_gemm1_kernel<<<8 * 64 * 64, 256>>>(x, w1, w3);
    // GEMM2: grid = E(8) * m_tiles_max(64) * n_tiles(16), n fastest
    moe_gemm2_kernel<<<8 * 64 * 16, 256>>>(w2, out);
}